// round 1
// baseline (speedup 1.0000x reference)
#include <cuda_runtime.h>
#include <math.h>

#define DEG2RAD_F 0.017453292519943295f
#define INV_SQRT_D 0.08838834764831845f

// scratch: S = attn @ V per batch  (1024 x 50 x 128 floats = 26.2 MB)
__device__ float g_S[1024 * 50 * 128];

// sin(h) for |h| <= ~0.01 rad: h*(1 - h^2/6 + h^4/120), rel err ~1e-10
__device__ __forceinline__ float sin_small(float h) {
    float hh = h * h;
    return h * fmaf(hh, fmaf(hh, 8.3333333e-3f, -0.166666667f), 1.0f);
}

// linear interp over a 64-entry table, matching jax _interp_scalar
__device__ __forceinline__ float interp64(const float* __restrict__ t, float x) {
    x = fminf(fmaxf(x, 0.0f), 62.999999f);
    int k = (int)x;              // floor (x >= 0)
    float f = x - (float)k;
    return fmaf(f, t[k + 1] - t[k], t[k]);
}

// out[n][d] = sum_k sx[n][k] * W[d][k]; each thread owns column d, 25 rows.
// MODE 0: out[n*128+d]   MODE 1 (K transposed): out[d*53+n]
template <int MODE>
__device__ __forceinline__ void small_gemm(const float* __restrict__ W,
                                           const float* __restrict__ sx,
                                           float* __restrict__ out,
                                           int d, int half) {
    float acc[25];
#pragma unroll
    for (int i = 0; i < 25; i++) acc[i] = 0.f;
    const float* wrow = W + d * 128;
    for (int k0 = 0; k0 < 128; k0 += 8) {
        float4 w0 = *(const float4*)(wrow + k0);
        float4 w1 = *(const float4*)(wrow + k0 + 4);
#pragma unroll
        for (int i = 0; i < 25; i++) {
            const float* xr = sx + (half + 2 * i) * 128 + k0;
            float4 x0 = *(const float4*)xr;
            float4 x1 = *(const float4*)(xr + 4);
            float a = acc[i];
            a = fmaf(x0.x, w0.x, a); a = fmaf(x0.y, w0.y, a);
            a = fmaf(x0.z, w0.z, a); a = fmaf(x0.w, w0.w, a);
            a = fmaf(x1.x, w1.x, a); a = fmaf(x1.y, w1.y, a);
            a = fmaf(x1.z, w1.z, a); a = fmaf(x1.w, w1.w, a);
            acc[i] = a;
        }
    }
#pragma unroll
    for (int i = 0; i < 25; i++) {
        int n = half + 2 * i;
        if (MODE == 0) out[n * 128 + d] = acc[i];
        else           out[d * 53 + n]  = acc[i];
    }
}

// ---------------- Kernel 1: per-batch attention, writes S ----------------
// grid = 1024 blocks, 256 threads, ~117 KB dynamic smem
__global__ void __launch_bounds__(256, 1)
stan_k1(const int* __restrict__ poi_idx, const int* __restrict__ hour,
        const float* __restrict__ lat, const float* __restrict__ lon,
        const float* __restrict__ tmin,
        const float* __restrict__ poi_emb, const float* __restrict__ time_emb,
        const float* __restrict__ E_t, const float* __restrict__ E_d,
        const float* __restrict__ Wq, const float* __restrict__ Wk,
        const float* __restrict__ Wv) {
    extern __shared__ float sm[];
    float* sx  = sm;            // 50*128
    float* sQ  = sm + 6400;     // 50*128
    float* sKt = sm + 12800;    // 128*53 (transposed, padded)
    float* sV  = sm + 19584;    // 50*128
    float* sA  = sm + 25984;    // 50*52 scores/attn
    float* slat = sm + 28584;
    float* slon = sm + 28648;
    float* st   = sm + 28712;
    float* scs  = sm + 28776;
    float* sEt  = sm + 28840;
    float* sEd  = sm + 28904;
    int* spad = (int*)(sm + 28968);
    int* spoi = (int*)(sm + 29032);
    int* shr  = (int*)(sm + 29096);

    const int b = blockIdx.x;
    const int tid = threadIdx.x;

    if (tid < 64) { sEt[tid] = E_t[tid]; sEd[tid] = E_d[tid]; }
    if (tid < 50) {
        int p = poi_idx[b * 50 + tid];
        int h = hour[b * 50 + tid];
        int pad = (p < 0);
        spad[tid] = pad;
        spoi[tid] = pad ? 50000 : p;
        shr[tid]  = pad ? 0 : h;
        float la = lat[b * 50 + tid];
        slat[tid] = la;
        slon[tid] = lon[b * 50 + tid];
        st[tid]   = tmin[b * 50 + tid];
        scs[tid]  = cosf(la * DEG2RAD_F);
    }
    __syncthreads();

    // gather x = poi_emb[poi] + time_emb[hour]
    for (int idx = tid; idx < 6400; idx += 256) {
        int n = idx >> 7, d = idx & 127;
        sx[idx] = poi_emb[spoi[n] * 128 + d] + time_emb[shr[n] * 128 + d];
    }
    __syncthreads();

    const int d = tid & 127;
    const int half = tid >> 7;
    small_gemm<0>(Wq, sx, sQ, d, half);
    small_gemm<1>(Wk, sx, sKt, d, half);
    small_gemm<0>(Wv, sx, sV, d, half);
    __syncthreads();

    // scores[n][m] = Q[n].K[m]/sqrt(D) + bias(n,m); -inf where pad[m]
    {
        const int m0 = tid & 63;
        const int grp = tid >> 6;
        const int m = (m0 < 50) ? m0 : 0;
        float acc[13];
#pragma unroll
        for (int i = 0; i < 13; i++) acc[i] = 0.f;
        for (int d0 = 0; d0 < 128; d0 += 8) {
            float kt[8];
#pragma unroll
            for (int j = 0; j < 8; j++) kt[j] = sKt[(d0 + j) * 53 + m];
            int i = 0;
            for (int n = grp; n < 50; n += 4, i++) {
                const float* qr = sQ + n * 128 + d0;
                float4 q0 = *(const float4*)qr;
                float4 q1 = *(const float4*)(qr + 4);
                float a = acc[i];
                a = fmaf(q0.x, kt[0], a); a = fmaf(q0.y, kt[1], a);
                a = fmaf(q0.z, kt[2], a); a = fmaf(q0.w, kt[3], a);
                a = fmaf(q1.x, kt[4], a); a = fmaf(q1.y, kt[5], a);
                a = fmaf(q1.z, kt[6], a); a = fmaf(q1.w, kt[7], a);
                acc[i] = a;
            }
        }
        if (m0 < 50) {
            float tm = st[m0], lam = slat[m0], lom = slon[m0], cm = scs[m0];
            int padm = spad[m0];
            int i = 0;
            for (int n = grp; n < 50; n += 4, i++) {
                float vp = (spad[n] | padm) ? 0.f : 1.f;
                float dt = fabsf(st[n] - tm) * vp;
                float dlh  = (lam - slat[n]) * (0.5f * DEG2RAD_F);
                float dloh = (lom - slon[n]) * (0.5f * DEG2RAD_F);
                float s1 = sin_small(dlh), s2 = sin_small(dloh);
                float a = fmaf(scs[n] * cm, s2 * s2, s1 * s1);
                a = fminf(fmaxf(a, 0.f), 1.f);
                float dd = 12742.0f * asinf(sqrtf(a)) * vp;
                float bias = interp64(sEt, dt * (63.0f / 10080.0f))
                           + interp64(sEd, dd * (63.0f / 200.0f));
                float sc = fmaf(acc[i], INV_SQRT_D, bias);
                if (padm) sc = -INFINITY;
                sA[n * 52 + m0] = sc;
            }
        }
    }
    __syncthreads();

    // row softmax (warp per row)
    {
        int w = tid >> 5, lane = tid & 31;
        for (int n = w; n < 50; n += 8) {
            float v0 = (lane < 50)      ? sA[n * 52 + lane]      : -INFINITY;
            float v1 = (lane + 32 < 50) ? sA[n * 52 + lane + 32] : -INFINITY;
            float mx = fmaxf(v0, v1);
#pragma unroll
            for (int o = 16; o > 0; o >>= 1)
                mx = fmaxf(mx, __shfl_xor_sync(0xffffffffu, mx, o));
            float e0 = (mx == -INFINITY) ? 0.f : expf(v0 - mx);
            float e1 = (mx == -INFINITY) ? 0.f : expf(v1 - mx);
            float s = e0 + e1;
#pragma unroll
            for (int o = 16; o > 0; o >>= 1)
                s += __shfl_xor_sync(0xffffffffu, s, o);
            float inv = (s > 0.f) ? 1.f / s : 0.f;
            if (lane < 50)      sA[n * 52 + lane]      = e0 * inv;
            if (lane + 32 < 50) sA[n * 52 + lane + 32] = e1 * inv;
        }
    }
    __syncthreads();

    // S = attn @ V  -> global scratch
    {
        float acc[25];
#pragma unroll
        for (int i = 0; i < 25; i++) acc[i] = 0.f;
        for (int mm = 0; mm < 50; mm++) {
            float v = sV[mm * 128 + d];
#pragma unroll
            for (int i = 0; i < 25; i++)
                acc[i] = fmaf(sA[(half + 2 * i) * 52 + mm], v, acc[i]);
        }
        float* gS = g_S + b * 6400;
#pragma unroll
        for (int i = 0; i < 25; i++)
            gS[(half + 2 * i) * 128 + d] = acc[i];
    }
}

// ---------------- Kernel 2: matching GEMM + fused softmax-over-n ----------------
// grid = (8, 1024), 128 threads, ~93 KB smem (2 blocks/SM)
__global__ void __launch_bounds__(128, 2)
stan_k2(const int* __restrict__ poi_idx,
        const float* __restrict__ lat, const float* __restrict__ lon,
        const float* __restrict__ cent,
        const float* __restrict__ E_dm,
        const float* __restrict__ region_emb,
        float* __restrict__ out) {
    extern __shared__ float sm[];
    float* sS   = sm;            // 50*128
    float* sRe  = sm + 6400;     // 128*129 transposed region tile
    float* slat = sm + 22912;
    float* slon = sm + 22976;
    float* scs  = sm + 23040;
    float* sEdm = sm + 23104;
    int* spad   = (int*)(sm + 23168);

    const int b = blockIdx.y;
    const int r0 = blockIdx.x * 128;
    const int tid = threadIdx.x;

    if (tid < 64) sEdm[tid] = E_dm[tid];
    if (tid < 50) {
        float la = lat[b * 50 + tid];
        slat[tid] = la;
        slon[tid] = lon[b * 50 + tid];
        scs[tid]  = cosf(la * DEG2RAD_F);
        spad[tid] = (poi_idx[b * 50 + tid] < 0);
    }
    const float* gS = g_S + b * 6400;
    for (int idx = tid; idx < 6400; idx += 128) sS[idx] = gS[idx];
    for (int idx = tid; idx < 16384; idx += 128) {
        int rl = idx >> 7, dd = idx & 127;
        int r = r0 + rl;
        sRe[dd * 129 + rl] = (r < 1000) ? region_emb[r * 128 + dd] : 0.f;
    }
    __syncthreads();

    float acc[50];
#pragma unroll
    for (int n = 0; n < 50; n++) acc[n] = 0.f;
    for (int d0 = 0; d0 < 128; d0 += 4) {
        float r0v = sRe[(d0 + 0) * 129 + tid];
        float r1v = sRe[(d0 + 1) * 129 + tid];
        float r2v = sRe[(d0 + 2) * 129 + tid];
        float r3v = sRe[(d0 + 3) * 129 + tid];
#pragma unroll
        for (int n = 0; n < 50; n++) {
            float4 s = *(const float4*)(sS + n * 128 + d0);
            float a = acc[n];
            a = fmaf(s.x, r0v, a); a = fmaf(s.y, r1v, a);
            a = fmaf(s.z, r2v, a); a = fmaf(s.w, r3v, a);
            acc[n] = a;
        }
    }

    const int r = r0 + tid;
    if (r < 1000) {
        float cla = cent[r * 2], clo = cent[r * 2 + 1];
        float cc = cosf(cla * DEG2RAD_F);
        float mx = -INFINITY;
#pragma unroll
        for (int n = 0; n < 50; n++) {
            float dlh  = (cla - slat[n]) * (0.5f * DEG2RAD_F);
            float dloh = (clo - slon[n]) * (0.5f * DEG2RAD_F);
            float s1 = sin_small(dlh), s2 = sin_small(dloh);
            float a = fmaf(scs[n] * cc, s2 * s2, s1 * s1);
            a = fminf(fmaxf(a, 0.f), 1.f);
            float ddk = 12742.0f * asinf(sqrtf(a));
            float bias = interp64(sEdm, ddk * (63.0f / 200.0f));
            float v = fmaf(acc[n], INV_SQRT_D, bias);
            if (spad[n]) v = -INFINITY;
            acc[n] = v;
            mx = fmaxf(mx, v);
        }
        float sum = 0.f, ws = 0.f;
        if (mx != -INFINITY) {
#pragma unroll
            for (int n = 0; n < 50; n++) {
                if (!spad[n]) {
                    float e = expf(acc[n] - mx);
                    sum += e;
                    ws = fmaf(e, acc[n], ws);
                }
            }
        }
        out[b * 1000 + r] = (sum > 0.f) ? ws / sum : 0.f;
    }
}

#define SMEM1_BYTES (29160 * 4)
#define SMEM2_BYTES (23232 * 4)

extern "C" void kernel_launch(void* const* d_in, const int* in_sizes, int n_in,
                              void* d_out, int out_size) {
    const int*   poi  = (const int*)  d_in[0];
    const int*   hr   = (const int*)  d_in[1];
    const float* lat  = (const float*)d_in[2];
    const float* lon  = (const float*)d_in[3];
    const float* tmin = (const float*)d_in[4];
    const float* cent = (const float*)d_in[5];
    const float* pemb = (const float*)d_in[6];
    const float* temb = (const float*)d_in[7];
    const float* Et   = (const float*)d_in[8];
    const float* Ed   = (const float*)d_in[9];
    const float* Edm  = (const float*)d_in[10];
    const float* remb = (const float*)d_in[11];
    const float* Wq   = (const float*)d_in[12];
    const float* Wk   = (const float*)d_in[13];
    const float* Wv   = (const float*)d_in[14];
    float* out = (float*)d_out;

    cudaFuncSetAttribute(stan_k1, cudaFuncAttributeMaxDynamicSharedMemorySize, SMEM1_BYTES);
    cudaFuncSetAttribute(stan_k2, cudaFuncAttributeMaxDynamicSharedMemorySize, SMEM2_BYTES);

    stan_k1<<<1024, 256, SMEM1_BYTES>>>(poi, hr, lat, lon, tmin,
                                        pemb, temb, Et, Ed, Wq, Wk, Wv);
    stan_k2<<<dim3(8, 1024), 128, SMEM2_BYTES>>>(poi, lat, lon, cent, Edm, remb, out);
}

// round 3
// speedup vs baseline: 1.3284x; 1.3284x over previous
#include <cuda_runtime.h>
#include <math.h>

#define DEG2RAD_F 0.017453292519943295f
#define HALF_D2R  0.008726646259971648f
#define INV_SQRT_D 0.08838834764831845f

typedef unsigned long long ull;

// scratch: S = attn @ V per batch  (1024 x 50 x 128 floats = 26.2 MB)
__device__ float g_S[1024 * 50 * 128];

// ---- packed f32x2 helpers (SASS FFMA2 — PTX-only) ----
__device__ __forceinline__ ull fma2(ull a, ull b, ull c) {
    ull d;
    asm("fma.rn.f32x2 %0, %1, %2, %3;" : "=l"(d) : "l"(a), "l"(b), "l"(c));
    return d;
}
__device__ __forceinline__ ull pack2(float lo, float hi) {
    ull d;
    asm("mov.b64 %0, {%1, %2};" : "=l"(d) : "r"(__float_as_uint(lo)), "r"(__float_as_uint(hi)));
    return d;
}
__device__ __forceinline__ float unpack_sum(ull a) {
    unsigned lo, hi;
    asm("mov.b64 {%0, %1}, %2;" : "=r"(lo), "=r"(hi) : "l"(a));
    return __uint_as_float(lo) + __uint_as_float(hi);
}

// ---- cheap math (valid: all coords within ~1.6 deg box) ----
__device__ __forceinline__ float sin_small(float h) {        // |h| <= 0.01 rad
    float hh = h * h;
    return h * fmaf(hh, fmaf(hh, 8.3333333e-3f, -0.16666667f), 1.0f);
}
__device__ __forceinline__ float cos_small(float h) {        // |h| <= 0.018 rad
    float hh = h * h;
    return fmaf(hh, fmaf(hh, 4.1666668e-2f, -0.5f), 1.0f);
}
__device__ __forceinline__ float sqrt_approx(float a) {
    float r;
    asm("sqrt.approx.f32 %0, %1;" : "=f"(r) : "f"(a));
    return r;
}
// haversine km; dlh/dloh are half-angle radians, cc = cos(lat1)*cos(lat2)
__device__ __forceinline__ float hav_km(float dlh, float dloh, float cc) {
    float s1 = sin_small(dlh), s2 = sin_small(dloh);
    float a = fmaf(cc, s2 * s2, s1 * s1);             // a in [0, ~1.6e-4]
    // 2R*asin(sqrt(a)) ~= 2R*sqrt(a)*(1 + a/6),  rel err ~2e-9 on this domain
    return sqrt_approx(a) * fmaf(a, 2123.6667f, 12742.0f);
}
// interp over 64-entry table stored as (t[k], t[k+1]) pairs; x >= 0
__device__ __forceinline__ float interp2(const float2* __restrict__ t, float x) {
    x = fminf(x, 62.999996f);
    int k = (int)x;
    float f = x - (float)k;
    float2 p = t[k];
    return fmaf(f, p.y - p.x, p.x);
}

// out[n][d] = sum_k sx[n][k] * W[d][k]; thread owns column d, rows half+2i.
// sx stride 128, out stride 132. Packed along k.
__device__ __forceinline__ void small_gemm(const float* __restrict__ W,
                                           const float* __restrict__ sx,
                                           float* __restrict__ out,
                                           int d, int half) {
    ull acc2[25];
#pragma unroll
    for (int i = 0; i < 25; i++) acc2[i] = 0ull;
    const float* wrow = W + d * 128;
    for (int k0 = 0; k0 < 128; k0 += 8) {
        ulonglong2 w0 = *(const ulonglong2*)(wrow + k0);
        ulonglong2 w1 = *(const ulonglong2*)(wrow + k0 + 4);
#pragma unroll
        for (int i = 0; i < 25; i++) {
            const float* xr = sx + (half + 2 * i) * 128 + k0;
            ulonglong2 x0 = *(const ulonglong2*)xr;
            ulonglong2 x1 = *(const ulonglong2*)(xr + 4);
            ull a = acc2[i];
            a = fma2(x0.x, w0.x, a); a = fma2(x0.y, w0.y, a);
            a = fma2(x1.x, w1.x, a); a = fma2(x1.y, w1.y, a);
            acc2[i] = a;
        }
    }
#pragma unroll
    for (int i = 0; i < 25; i++)
        out[(half + 2 * i) * 132 + d] = unpack_sum(acc2[i]);
}

// ---------------- Kernel 1: per-batch attention, writes S ----------------
// smem layout (floats):
//   sx   @ 0      (50*128=6400)  -- reused as sA (50*52) after GEMMs
//   sQ   @ 6400   (50*132=6600)
//   sK   @ 13000  (6600)
//   sV   @ 19600  (6600)
//   Et2  @ 26200  (128)  Ed2 @ 26328 (128)
//   st   @ 26456  slh @ 26520  sloh @ 26584  scs @ 26648
//   spad @ 26712  spoi @ 26776  shr @ 26840       total 26904 floats
__global__ void __launch_bounds__(256, 2)
stan_k1(const int* __restrict__ poi_idx, const int* __restrict__ hour,
        const float* __restrict__ lat, const float* __restrict__ lon,
        const float* __restrict__ tmin,
        const float* __restrict__ poi_emb, const float* __restrict__ time_emb,
        const float* __restrict__ E_t, const float* __restrict__ E_d,
        const float* __restrict__ Wq, const float* __restrict__ Wk,
        const float* __restrict__ Wv) {
    extern __shared__ float sm[];
    float2* sEt2 = (float2*)(sm + 26200);
    float2* sEd2 = (float2*)(sm + 26328);
    float* st   = sm + 26456;
    float* slh  = sm + 26520;
    float* sloh = sm + 26584;
    float* scs  = sm + 26648;
    int* spad = (int*)(sm + 26712);
    int* spoi = (int*)(sm + 26776);
    int* shr  = (int*)(sm + 26840);

    const int b = blockIdx.x;
    const int tid = threadIdx.x;

    if (tid < 64) {
        sEt2[tid] = make_float2(E_t[tid], E_t[min(tid + 1, 63)]);
        sEd2[tid] = make_float2(E_d[tid], E_d[min(tid + 1, 63)]);
    }
    if (tid < 50) {
        int p = poi_idx[b * 50 + tid];
        int h = hour[b * 50 + tid];
        int pad = (p < 0);
        spad[tid] = pad;
        spoi[tid] = pad ? 50000 : p;
        shr[tid]  = pad ? 0 : h;
        float la = lat[b * 50 + tid];
        float lo = lon[b * 50 + tid];
        slh[tid]  = la * HALF_D2R;
        sloh[tid] = lo * HALF_D2R;
        scs[tid]  = cos_small(la * DEG2RAD_F);
        st[tid]   = tmin[b * 50 + tid];
    }
    __syncthreads();

    // gather x = poi_emb[poi] + time_emb[hour] into sx (stride 128)
    for (int idx = tid; idx < 6400; idx += 256) {
        int n = idx >> 7, d = idx & 127;
        sm[idx] = poi_emb[spoi[n] * 128 + d] + time_emb[shr[n] * 128 + d];
    }
    __syncthreads();

    const int d = tid & 127;
    const int half = tid >> 7;
    small_gemm(Wq, sm, sm + 6400, d, half);
    small_gemm(Wk, sm, sm + 13000, d, half);
    small_gemm(Wv, sm, sm + 19600, d, half);
    __syncthreads();

    float* sA = sm;  // overwrite sx

    // scores[n][m] = Q[n].K[m]/sqrt(D) + bias(n,m); -inf where pad[m]
    {
        const int m0 = tid & 63;
        const int grp = tid >> 6;
        const int m = (m0 < 50) ? m0 : 0;
        const float* sQb = sm + 6400;
        const float* sKb = sm + 13000;
        ull acc2[13];
#pragma unroll
        for (int i = 0; i < 13; i++) acc2[i] = 0ull;
        for (int d0 = 0; d0 < 128; d0 += 8) {
            ulonglong2 k0 = *(const ulonglong2*)(sKb + m * 132 + d0);
            ulonglong2 k1 = *(const ulonglong2*)(sKb + m * 132 + d0 + 4);
            int i = 0;
            for (int n = grp; n < 50; n += 4, i++) {
                const float* qr = sQb + n * 132 + d0;
                ulonglong2 q0 = *(const ulonglong2*)qr;
                ulonglong2 q1 = *(const ulonglong2*)(qr + 4);
                ull a = acc2[i];
                a = fma2(q0.x, k0.x, a); a = fma2(q0.y, k0.y, a);
                a = fma2(q1.x, k1.x, a); a = fma2(q1.y, k1.y, a);
                acc2[i] = a;
            }
        }
        if (m0 < 50) {
            float tm = st[m0], lhm = slh[m0], lom = sloh[m0], cm = scs[m0];
            int padm = spad[m0];
            int i = 0;
            for (int n = grp; n < 50; n += 4, i++) {
                float vp = (spad[n] | padm) ? 0.f : 1.f;
                float dt = fabsf(st[n] - tm) * vp;
                float dd = hav_km(lhm - slh[n], lom - sloh[n], scs[n] * cm) * vp;
                float bias = interp2(sEt2, dt * (63.0f / 10080.0f))
                           + interp2(sEd2, dd * (63.0f / 200.0f));
                float sc = fmaf(unpack_sum(acc2[i]), INV_SQRT_D, bias);
                if (padm) sc = -INFINITY;
                sA[n * 52 + m0] = sc;
            }
        }
    }
    __syncthreads();

    // row softmax (warp per row)
    {
        int w = tid >> 5, lane = tid & 31;
        for (int n = w; n < 50; n += 8) {
            float v0 = (lane < 50)      ? sA[n * 52 + lane]      : -INFINITY;
            float v1 = (lane + 32 < 50) ? sA[n * 52 + lane + 32] : -INFINITY;
            float mx = fmaxf(v0, v1);
#pragma unroll
            for (int o = 16; o > 0; o >>= 1)
                mx = fmaxf(mx, __shfl_xor_sync(0xffffffffu, mx, o));
            float e0 = (mx == -INFINITY) ? 0.f : __expf(v0 - mx);
            float e1 = (mx == -INFINITY) ? 0.f : __expf(v1 - mx);
            float s = e0 + e1;
#pragma unroll
            for (int o = 16; o > 0; o >>= 1)
                s += __shfl_xor_sync(0xffffffffu, s, o);
            float inv = (s > 0.f) ? 1.f / s : 0.f;
            if (lane < 50)      sA[n * 52 + lane]      = e0 * inv;
            if (lane + 32 < 50) sA[n * 52 + lane + 32] = e1 * inv;
        }
    }
    __syncthreads();

    // S = attn @ V -> global scratch (packed along m)
    {
        const float* sVb = sm + 19600;
        ull acc2[25];
#pragma unroll
        for (int i = 0; i < 25; i++) acc2[i] = 0ull;
        for (int m = 0; m < 50; m += 2) {
            ull v2 = pack2(sVb[m * 132 + d], sVb[(m + 1) * 132 + d]);
#pragma unroll
            for (int i = 0; i < 25; i++) {
                ull a2 = *(const ull*)(sA + (half + 2 * i) * 52 + m);
                acc2[i] = fma2(a2, v2, acc2[i]);
            }
        }
        float* gS = g_S + b * 6400;
#pragma unroll
        for (int i = 0; i < 25; i++)
            gS[(half + 2 * i) * 128 + d] = unpack_sum(acc2[i]);
    }
}

// ---------------- Kernel 2: matching GEMM + fused softmax-over-n ----------------
// 256 threads, r-tile 128, 2 threads per r (25 n's each), grid (8, 1024).
// smem (floats): sS @ 0 (50*132=6600), Edm2 @ 6600 (128),
//                slh @ 6728, sloh @ 6792, scs @ 6856, spad @ 6920  -> 6984 floats
__global__ void __launch_bounds__(256, 3)
stan_k2(const int* __restrict__ poi_idx,
        const float* __restrict__ lat, const float* __restrict__ lon,
        const float* __restrict__ cent,
        const float* __restrict__ E_dm,
        const float* __restrict__ region_emb,
        float* __restrict__ out) {
    extern __shared__ float sm[];
    float2* sEdm2 = (float2*)(sm + 6600);
    float* slh  = sm + 6728;
    float* sloh = sm + 6792;
    float* scs  = sm + 6856;
    int* spad   = (int*)(sm + 6920);

    const int b = blockIdx.y;
    const int r0 = blockIdx.x * 128;
    const int tid = threadIdx.x;

    if (tid < 64) sEdm2[tid] = make_float2(E_dm[tid], E_dm[min(tid + 1, 63)]);
    if (tid < 50) {
        float la = lat[b * 50 + tid];
        float lo = lon[b * 50 + tid];
        slh[tid]  = la * HALF_D2R;
        sloh[tid] = lo * HALF_D2R;
        scs[tid]  = cos_small(la * DEG2RAD_F);
        spad[tid] = (poi_idx[b * 50 + tid] < 0);
    }
    const float* gS = g_S + b * 6400;
    for (int idx = tid; idx < 6400; idx += 256)
        sm[(idx >> 7) * 132 + (idx & 127)] = gS[idx];
    __syncthreads();

    const int rl = tid >> 1;
    const int half = tid & 1;
    const int r = r0 + rl;
    const int rc = min(r, 999);
    const float* gRe = region_emb + rc * 128;
    const float* sp = sm + half * 132;     // row n = 2i+half -> sp + i*264

    ull acc2[25];
#pragma unroll
    for (int i = 0; i < 25; i++) acc2[i] = 0ull;

    ulonglong2 re = *(const ulonglong2*)gRe;
    for (int d0 = 0; d0 < 128; d0 += 4) {
        ulonglong2 re_n = re;
        if (d0 + 4 < 128) re_n = *(const ulonglong2*)(gRe + d0 + 4);
#pragma unroll
        for (int i = 0; i < 25; i++) {
            ulonglong2 s = *(const ulonglong2*)(sp + i * 264 + d0);
            ull a = acc2[i];
            a = fma2(s.x, re.x, a);
            a = fma2(s.y, re.y, a);
            acc2[i] = a;
        }
        re = re_n;
    }

    float accf[25];
#pragma unroll
    for (int i = 0; i < 25; i++) accf[i] = unpack_sum(acc2[i]);

    // epilogue: bias + masked softmax over n, fused weighted sum
    float cla = cent[rc * 2], clo = cent[rc * 2 + 1];
    float claH = cla * HALF_D2R, cloH = clo * HALF_D2R;
    float cc = cos_small(cla * DEG2RAD_F);
    float mx = -INFINITY;
#pragma unroll
    for (int i = 0; i < 25; i++) {
        int n = 2 * i + half;
        float dd = hav_km(claH - slh[n], cloH - sloh[n], cc * scs[n]);
        float bias = interp2(sEdm2, dd * (63.0f / 200.0f));
        float sc = fmaf(accf[i], INV_SQRT_D, bias);
        if (spad[n]) sc = -INFINITY;
        accf[i] = sc;
        mx = fmaxf(mx, sc);
    }
    mx = fmaxf(mx, __shfl_xor_sync(0xffffffffu, mx, 1));

    float sum = 0.f, ws = 0.f;
    if (mx != -INFINITY) {
#pragma unroll
        for (int i = 0; i < 25; i++) {
            int n = 2 * i + half;
            if (!spad[n]) {
                float e = __expf(accf[i] - mx);
                sum += e;
                ws = fmaf(e, accf[i], ws);
            }
        }
    }
    sum += __shfl_xor_sync(0xffffffffu, sum, 1);
    ws  += __shfl_xor_sync(0xffffffffu, ws, 1);
    if (half == 0 && r < 1000)
        out[b * 1000 + r] = (sum > 0.f) ? ws / sum : 0.f;
}

#define SMEM1_BYTES (26904 * 4)
#define SMEM2_BYTES (6984 * 4)

extern "C" void kernel_launch(void* const* d_in, const int* in_sizes, int n_in,
                              void* d_out, int out_size) {
    const int*   poi  = (const int*)  d_in[0];
    const int*   hr   = (const int*)  d_in[1];
    const float* lat  = (const float*)d_in[2];
    const float* lon  = (const float*)d_in[3];
    const float* tmin = (const float*)d_in[4];
    const float* cent = (const float*)d_in[5];
    const float* pemb = (const float*)d_in[6];
    const float* temb = (const float*)d_in[7];
    const float* Et   = (const float*)d_in[8];
    const float* Ed   = (const float*)d_in[9];
    const float* Edm  = (const float*)d_in[10];
    const float* remb = (const float*)d_in[11];
    const float* Wq   = (const float*)d_in[12];
    const float* Wk   = (const float*)d_in[13];
    const float* Wv   = (const float*)d_in[14];
    float* out = (float*)d_out;

    cudaFuncSetAttribute(stan_k1, cudaFuncAttributeMaxDynamicSharedMemorySize, SMEM1_BYTES);
    cudaFuncSetAttribute(stan_k2, cudaFuncAttributeMaxDynamicSharedMemorySize, SMEM2_BYTES);

    stan_k1<<<1024, 256, SMEM1_BYTES>>>(poi, hr, lat, lon, tmin,
                                        pemb, temb, Et, Ed, Wq, Wk, Wv);
    stan_k2<<<dim3(8, 1024), 256, SMEM2_BYTES>>>(poi, lat, lon, cent, Edm, remb, out);
}

// round 5
// speedup vs baseline: 1.4940x; 1.1246x over previous
#include <cuda_runtime.h>
#include <math.h>

#define DEG2RAD_F 0.017453292519943295f
#define HALF_D2R  0.008726646259971648f
#define INV_SQRT_D 0.08838834764831845f

typedef unsigned long long ull;

// scratch: S = attn @ V per batch  (1024 x 50 x 128 floats = 26.2 MB)
__device__ float g_S[1024 * 50 * 128];

// ---- packed f32x2 helpers (SASS FFMA2 — PTX-only) ----
__device__ __forceinline__ ull fma2(ull a, ull b, ull c) {
    ull d;
    asm("fma.rn.f32x2 %0, %1, %2, %3;" : "=l"(d) : "l"(a), "l"(b), "l"(c));
    return d;
}
__device__ __forceinline__ ull pack2(float lo, float hi) {
    ull d;
    asm("mov.b64 %0, {%1, %2};" : "=l"(d) : "r"(__float_as_uint(lo)), "r"(__float_as_uint(hi)));
    return d;
}
__device__ __forceinline__ float unpack_sum(ull a) {
    unsigned lo, hi;
    asm("mov.b64 {%0, %1}, %2;" : "=r"(lo), "=r"(hi) : "l"(a));
    return __uint_as_float(lo) + __uint_as_float(hi);
}

// ---- cheap math (valid: all coords within ~1.6 deg box) ----
__device__ __forceinline__ float sin_small(float h) {
    float hh = h * h;
    return h * fmaf(hh, fmaf(hh, 8.3333333e-3f, -0.16666667f), 1.0f);
}
__device__ __forceinline__ float cos_small(float h) {
    float hh = h * h;
    return fmaf(hh, fmaf(hh, 4.1666668e-2f, -0.5f), 1.0f);
}
__device__ __forceinline__ float sqrt_approx(float a) {
    float r;
    asm("sqrt.approx.f32 %0, %1;" : "=f"(r) : "f"(a));
    return r;
}
__device__ __forceinline__ float hav_km(float dlh, float dloh, float cc) {
    float s1 = sin_small(dlh), s2 = sin_small(dloh);
    float a = fmaf(cc, s2 * s2, s1 * s1);
    return sqrt_approx(a) * fmaf(a, 2123.6667f, 12742.0f);
}
__device__ __forceinline__ float interp2(const float2* __restrict__ t, float x) {
    x = fminf(x, 62.999996f);
    int k = (int)x;
    float f = x - (float)k;
    float2 p = t[k];
    return fmaf(f, p.y - p.x, p.x);
}

// out[n][d] = sum_k sx[n][k]*W[d][k], W staged through smem in 16-k chunks.
// sW layout: [128 d][20] (stride 20 words -> conflict-free 4-phase LDS.128).
__device__ __forceinline__ void gemm_staged(const float* __restrict__ gW,
                                            const float* __restrict__ sx,
                                            float* __restrict__ sW,
                                            float* __restrict__ out,
                                            int d, int half, int tid) {
    ull acc2[25];
#pragma unroll
    for (int i = 0; i < 25; i++) acc2[i] = 0ull;
#pragma unroll 1
    for (int c = 0; c < 8; c++) {
        const int kc = c * 16;
        __syncthreads();   // prior chunk's LDS reads done before overwrite
        {   // copy W[:, kc:kc+16] -> sW, coalesced float4
            int idx = tid;
#pragma unroll
            for (int rep = 0; rep < 2; rep++, idx += 256) {
                int dd = idx >> 2, j = (idx & 3) * 4;
                float4 v = *(const float4*)(gW + dd * 128 + kc + j);
                *(float4*)(sW + dd * 20 + j) = v;
            }
        }
        __syncthreads();
#pragma unroll
        for (int k0 = 0; k0 < 16; k0 += 8) {
            ulonglong2 w0 = *(const ulonglong2*)(sW + d * 20 + k0);
            ulonglong2 w1 = *(const ulonglong2*)(sW + d * 20 + k0 + 4);
#pragma unroll
            for (int i = 0; i < 25; i++) {
                const float* xr = sx + (half + 2 * i) * 128 + kc + k0;
                ulonglong2 x0 = *(const ulonglong2*)xr;
                ulonglong2 x1 = *(const ulonglong2*)(xr + 4);
                ull a = acc2[i];
                a = fma2(x0.x, w0.x, a); a = fma2(x0.y, w0.y, a);
                a = fma2(x1.x, w1.x, a); a = fma2(x1.y, w1.y, a);
                acc2[i] = a;
            }
        }
    }
#pragma unroll
    for (int i = 0; i < 25; i++)
        out[(half + 2 * i) * 132 + d] = unpack_sum(acc2[i]);
}

// ---------------- Kernel 1: per-batch attention, writes S ----------------
// smem (floats): sx@0 (6400, reused as sA 50*52 later), sQ@6400 (6600),
//   sK@13000 (6600), sV@19600 (6600), sW@26200 (2560),
//   Et2@28760(128), Ed2@28888(128), st@29016, slh@29080, sloh@29144,
//   scs@29208, spad@29272, spoi@29336, shr@29400  -> 29464 floats (117.9KB)
__global__ void __launch_bounds__(256, 1)
stan_k1(const int* __restrict__ poi_idx, const int* __restrict__ hour,
        const float* __restrict__ lat, const float* __restrict__ lon,
        const float* __restrict__ tmin,
        const float* __restrict__ poi_emb, const float* __restrict__ time_emb,
        const float* __restrict__ E_t, const float* __restrict__ E_d,
        const float* __restrict__ Wq, const float* __restrict__ Wk,
        const float* __restrict__ Wv) {
    extern __shared__ float sm[];
    float* sW = sm + 26200;
    float2* sEt2 = (float2*)(sm + 28760);
    float2* sEd2 = (float2*)(sm + 28888);
    float* st   = sm + 29016;
    float* slh  = sm + 29080;
    float* sloh = sm + 29144;
    float* scs  = sm + 29208;
    int* spad = (int*)(sm + 29272);
    int* spoi = (int*)(sm + 29336);
    int* shr  = (int*)(sm + 29400);

    const int b = blockIdx.x;
    const int tid = threadIdx.x;

    if (tid < 64) {
        sEt2[tid] = make_float2(E_t[tid], E_t[min(tid + 1, 63)]);
        sEd2[tid] = make_float2(E_d[tid], E_d[min(tid + 1, 63)]);
    }
    if (tid < 50) {
        int p = poi_idx[b * 50 + tid];
        int h = hour[b * 50 + tid];
        int pad = (p < 0);
        spad[tid] = pad;
        spoi[tid] = pad ? 50000 : p;
        shr[tid]  = pad ? 0 : h;
        float la = lat[b * 50 + tid];
        float lo = lon[b * 50 + tid];
        slh[tid]  = la * HALF_D2R;
        sloh[tid] = lo * HALF_D2R;
        scs[tid]  = cos_small(la * DEG2RAD_F);
        st[tid]   = tmin[b * 50 + tid];
    }
    __syncthreads();

    for (int idx = tid; idx < 6400; idx += 256) {
        int n = idx >> 7, d = idx & 127;
        sm[idx] = poi_emb[spoi[n] * 128 + d] + time_emb[shr[n] * 128 + d];
    }

    const int d = tid & 127;
    const int half = tid >> 7;
    gemm_staged(Wq, sm, sW, sm + 6400, d, half, tid);   // first sync inside covers gather
    gemm_staged(Wk, sm, sW, sm + 13000, d, half, tid);
    gemm_staged(Wv, sm, sW, sm + 19600, d, half, tid);
    __syncthreads();

    float* sA = sm;  // overwrite sx

    // scores[n][m] = Q[n].K[m]/sqrt(D) + bias(n,m); -inf where pad[m]
    {
        const int m0 = tid & 63;
        const int grp = tid >> 6;
        const int m = (m0 < 50) ? m0 : 0;
        const float* sQb = sm + 6400;
        const float* sKb = sm + 13000;
        ull acc2[13];
#pragma unroll
        for (int i = 0; i < 13; i++) acc2[i] = 0ull;
        for (int d0 = 0; d0 < 128; d0 += 8) {
            ulonglong2 k0 = *(const ulonglong2*)(sKb + m * 132 + d0);
            ulonglong2 k1 = *(const ulonglong2*)(sKb + m * 132 + d0 + 4);
            int i = 0;
            for (int n = grp; n < 50; n += 4, i++) {
                const float* qr = sQb + n * 132 + d0;
                ulonglong2 q0 = *(const ulonglong2*)qr;
                ulonglong2 q1 = *(const ulonglong2*)(qr + 4);
                ull a = acc2[i];
                a = fma2(q0.x, k0.x, a); a = fma2(q0.y, k0.y, a);
                a = fma2(q1.x, k1.x, a); a = fma2(q1.y, k1.y, a);
                acc2[i] = a;
            }
        }
        if (m0 < 50) {
            float tm = st[m0], lhm = slh[m0], lom = sloh[m0], cm = scs[m0];
            int padm = spad[m0];
            int i = 0;
            for (int n = grp; n < 50; n += 4, i++) {
                float vp = (spad[n] | padm) ? 0.f : 1.f;
                float dt = fabsf(st[n] - tm) * vp;
                float dd = hav_km(lhm - slh[n], lom - sloh[n], scs[n] * cm) * vp;
                float bias = interp2(sEt2, dt * (63.0f / 10080.0f))
                           + interp2(sEd2, dd * (63.0f / 200.0f));
                float sc = fmaf(unpack_sum(acc2[i]), INV_SQRT_D, bias);
                if (padm) sc = -INFINITY;
                sA[n * 52 + m0] = sc;
            }
        }
    }
    __syncthreads();

    // row softmax (warp per row)
    {
        int w = tid >> 5, lane = tid & 31;
        for (int n = w; n < 50; n += 8) {
            float v0 = (lane < 50)      ? sA[n * 52 + lane]      : -INFINITY;
            float v1 = (lane + 32 < 50) ? sA[n * 52 + lane + 32] : -INFINITY;
            float mx = fmaxf(v0, v1);
#pragma unroll
            for (int o = 16; o > 0; o >>= 1)
                mx = fmaxf(mx, __shfl_xor_sync(0xffffffffu, mx, o));
            float e0 = (mx == -INFINITY) ? 0.f : __expf(v0 - mx);
            float e1 = (mx == -INFINITY) ? 0.f : __expf(v1 - mx);
            float s = e0 + e1;
#pragma unroll
            for (int o = 16; o > 0; o >>= 1)
                s += __shfl_xor_sync(0xffffffffu, s, o);
            float inv = (s > 0.f) ? 1.f / s : 0.f;
            if (lane < 50)      sA[n * 52 + lane]      = e0 * inv;
            if (lane + 32 < 50) sA[n * 52 + lane + 32] = e1 * inv;
        }
    }
    __syncthreads();

    // S = attn @ V -> global scratch (packed along m)
    {
        const float* sVb = sm + 19600;
        ull acc2[25];
#pragma unroll
        for (int i = 0; i < 25; i++) acc2[i] = 0ull;
        for (int m = 0; m < 50; m += 2) {
            ull v2 = pack2(sVb[m * 132 + d], sVb[(m + 1) * 132 + d]);
#pragma unroll
            for (int i = 0; i < 25; i++) {
                ull a2 = *(const ull*)(sA + (half + 2 * i) * 52 + m);
                acc2[i] = fma2(a2, v2, acc2[i]);
            }
        }
        float* gS = g_S + b * 6400;
#pragma unroll
        for (int i = 0; i < 25; i++)
            gS[(half + 2 * i) * 128 + d] = unpack_sum(acc2[i]);
    }
}

// ---------------- Kernel 2: matching GEMM + fused softmax-over-n ----------------
// 256 threads, r-tile 128 (2 threads per r, 25 n each), grid (8, 1024).
// smem (floats): sS@0 (50*132=6600), sRe@6600 (128*132=16896),
//   Edm2@23496 (128), slh@23624, sloh@23688, scs@23752, spad@23816 -> 23880 (95.5KB)
__global__ void __launch_bounds__(256, 2)
stan_k2(const int* __restrict__ poi_idx,
        const float* __restrict__ lat, const float* __restrict__ lon,
        const float* __restrict__ cent,
        const float* __restrict__ E_dm,
        const float* __restrict__ region_emb,
        float* __restrict__ out) {
    extern __shared__ float sm[];
    float* sRe = sm + 6600;
    float2* sEdm2 = (float2*)(sm + 23496);
    float* slh  = sm + 23624;
    float* sloh = sm + 23688;
    float* scs  = sm + 23752;
    int* spad   = (int*)(sm + 23816);

    const int b = blockIdx.y;
    const int r0 = blockIdx.x * 128;
    const int tid = threadIdx.x;

    if (tid < 64) sEdm2[tid] = make_float2(E_dm[tid], E_dm[min(tid + 1, 63)]);
    if (tid < 50) {
        float la = lat[b * 50 + tid];
        float lo = lon[b * 50 + tid];
        slh[tid]  = la * HALF_D2R;
        sloh[tid] = lo * HALF_D2R;
        scs[tid]  = cos_small(la * DEG2RAD_F);
        spad[tid] = (poi_idx[b * 50 + tid] < 0);
    }
    // stage S (stride 132)
    const float* gS = g_S + b * 6400;
    for (int idx = tid; idx < 6400; idx += 256)
        sm[(idx >> 7) * 132 + (idx & 127)] = gS[idx];
    // stage region tile [128 r][128 d] -> sRe stride 132, coalesced float4
    for (int idx = tid; idx < 4096; idx += 256) {
        int row = idx >> 5, c4 = (idx & 31) * 4;
        int r = min(r0 + row, 999);
        float4 v = *(const float4*)(region_emb + r * 128 + c4);
        *(float4*)(sRe + row * 132 + c4) = v;
    }
    __syncthreads();

    const int rl = tid >> 1;
    const int half = tid & 1;
    const int r = r0 + rl;
    const int rc = min(r, 999);
    const float* sp = sm + half * 132;       // row n = 2i+half -> sp + i*264
    const float* rrow = sRe + rl * 132;

    ull acc2[25];
#pragma unroll
    for (int i = 0; i < 25; i++) acc2[i] = 0ull;

    for (int d0 = 0; d0 < 128; d0 += 4) {
        ulonglong2 re = *(const ulonglong2*)(rrow + d0);
#pragma unroll
        for (int i = 0; i < 25; i++) {
            ulonglong2 s = *(const ulonglong2*)(sp + i * 264 + d0);
            ull a = acc2[i];
            a = fma2(s.x, re.x, a);
            a = fma2(s.y, re.y, a);
            acc2[i] = a;
        }
    }

    float accf[25];
#pragma unroll
    for (int i = 0; i < 25; i++) accf[i] = unpack_sum(acc2[i]);

    // epilogue: bias + masked softmax over n, fused weighted sum
    float cla = cent[rc * 2], clo = cent[rc * 2 + 1];
    float claH = cla * HALF_D2R, cloH = clo * HALF_D2R;
    float cc = cos_small(cla * DEG2RAD_F);
    float mx = -INFINITY;
#pragma unroll
    for (int i = 0; i < 25; i++) {
        int n = 2 * i + half;
        float dd = hav_km(claH - slh[n], cloH - sloh[n], cc * scs[n]);
        float bias = interp2(sEdm2, dd * (63.0f / 200.0f));
        float sc = fmaf(accf[i], INV_SQRT_D, bias);
        if (spad[n]) sc = -INFINITY;
        accf[i] = sc;
        mx = fmaxf(mx, sc);
    }
    mx = fmaxf(mx, __shfl_xor_sync(0xffffffffu, mx, 1));

    float sum = 0.f, ws = 0.f;
    if (mx != -INFINITY) {
#pragma unroll
        for (int i = 0; i < 25; i++) {
            int n = 2 * i + half;
            if (!spad[n]) {
                float e = __expf(accf[i] - mx);
                sum += e;
                ws = fmaf(e, accf[i], ws);
            }
        }
    }
    sum += __shfl_xor_sync(0xffffffffu, sum, 1);
    ws  += __shfl_xor_sync(0xffffffffu, ws, 1);
    if (half == 0 && r < 1000)
        out[b * 1000 + r] = (sum > 0.f) ? ws / sum : 0.f;
}

#define SMEM1_BYTES (29464 * 4)
#define SMEM2_BYTES (23880 * 4)

extern "C" void kernel_launch(void* const* d_in, const int* in_sizes, int n_in,
                              void* d_out, int out_size) {
    const int*   poi  = (const int*)  d_in[0];
    const int*   hr   = (const int*)  d_in[1];
    const float* lat  = (const float*)d_in[2];
    const float* lon  = (const float*)d_in[3];
    const float* tmin = (const float*)d_in[4];
    const float* cent = (const float*)d_in[5];
    const float* pemb = (const float*)d_in[6];
    const float* temb = (const float*)d_in[7];
    const float* Et   = (const float*)d_in[8];
    const float* Ed   = (const float*)d_in[9];
    const float* Edm  = (const float*)d_in[10];
    const float* remb = (const float*)d_in[11];
    const float* Wq   = (const float*)d_in[12];
    const float* Wk   = (const float*)d_in[13];
    const float* Wv   = (const float*)d_in[14];
    float* out = (float*)d_out;

    cudaFuncSetAttribute(stan_k1, cudaFuncAttributeMaxDynamicSharedMemorySize, SMEM1_BYTES);
    cudaFuncSetAttribute(stan_k2, cudaFuncAttributeMaxDynamicSharedMemorySize, SMEM2_BYTES);

    stan_k1<<<1024, 256, SMEM1_BYTES>>>(poi, hr, lat, lon, tmin,
                                        pemb, temb, Et, Ed, Wq, Wk, Wv);
    stan_k2<<<dim3(8, 1024), 256, SMEM2_BYTES>>>(poi, lat, lon, cent, Edm, remb, out);
}